// round 1
// baseline (speedup 1.0000x reference)
#include <cuda_runtime.h>
#include <math.h>
#include <stdint.h>

#define T_TOK 4096
#define D_DIM 768
#define N_ST  16
#define E_EXP 4
#define DFF_F 3072
#define V_VOC 32000
#define NLYR  4
#define BSZ   2
#define SEQL  2048

// ---------------- scratch (no allocations allowed) ----------------
__device__ float g_h[T_TOK * D_DIM];
__device__ float g_delta[T_TOK * D_DIM];
__device__ float g_Bm[T_TOK * N_ST];
__device__ float g_Cm[T_TOK * N_ST];
__device__ float g_y[T_TOK * D_DIM];
__device__ float g_mout[T_TOK * D_DIM];
__device__ float g_H[T_TOK * DFF_F];
__device__ float g_w[T_TOK];
__device__ int   g_eid[T_TOK];
__device__ int   g_pos[T_TOK];
__device__ int   g_perm[T_TOK];
__device__ int   g_cnt[E_EXP];
__device__ int   g_offs[E_EXP];

// ---------------- embed gather ----------------
__global__ void embed_gather_k(const int* __restrict__ x,
                               const float* __restrict__ embed,
                               float* __restrict__ h) {
    int t = blockIdx.x;
    int tok = x[t];
    const float4* src = (const float4*)(embed + (size_t)tok * D_DIM);
    float4* dst = (float4*)(h + (size_t)t * D_DIM);
    dst[threadIdx.x] = src[threadIdx.x];   // 192 threads * 4 = 768
}

// ---------------- generic 64x64x16 fp32 GEMM ----------------
// MODE 0: dense NN (A[M,K] row-major, B[K,N] row-major) + bias + ACT
// MODE 1: dense NT (B[N,K] row-major), no bias/act (logits)
// MODE 2: MoE up: gather A rows via perm, bias+silu, compact C rows
// MODE 3: MoE down: compact A rows, scatter C rows via perm, (acc+bias)*w[tok]
// ACT: 0 none, 1 softplus, 2 silu
template<int MODE, int ACT>
__global__ void __launch_bounds__(256) gemm_k(
    const float* __restrict__ A, const float* __restrict__ B,
    const float* __restrict__ bias, float* __restrict__ C,
    int N, int K,
    const int* __restrict__ perm, const float* __restrict__ wsc,
    const int* __restrict__ cnt, const int* __restrict__ offs)
{
    __shared__ __align__(16) float As[16][68];
    __shared__ __align__(16) float Bs[16][64];
    const int tid = threadIdx.x;
    const int bn = blockIdx.x * 64;
    const int bm = blockIdx.y * 64;

    int cnt_e = 0, off_e = 0;
    if (MODE >= 2) {
        int e = blockIdx.z;
        cnt_e = cnt[e];
        off_e = offs[e];
        if (bm >= cnt_e) return;
        B += (size_t)e * K * N;
        bias += (size_t)e * N;
    }

    const int a_r = tid >> 2;          // 0..63
    const int a_c = (tid & 3) << 2;    // 0,4,8,12
    const float* Arow = A;
    bool a_ok = true;
    if (MODE == 0 || MODE == 1) {
        Arow = A + (size_t)(bm + a_r) * K;
    } else if (MODE == 2) {
        a_ok = (bm + a_r) < cnt_e;
        int tok = a_ok ? perm[off_e + bm + a_r] : 0;
        Arow = A + (size_t)tok * K;
    } else { // MODE 3
        a_ok = (bm + a_r) < cnt_e;
        Arow = A + (size_t)(off_e + bm + (a_ok ? a_r : 0)) * K;
    }
    const int b_r = tid >> 4;          // 0..15 (NN)
    const int b_c = (tid & 15) << 2;   // 0..60 (NN)
    const float* Brow_nt = B + (size_t)(bn + a_r) * K;  // NT path

    const int tx = tid & 15;
    const int ty = tid >> 4;
    float acc[4][4];
#pragma unroll
    for (int i = 0; i < 4; i++)
#pragma unroll
        for (int j = 0; j < 4; j++) acc[i][j] = 0.f;

    for (int k0 = 0; k0 < K; k0 += 16) {
        float4 av = make_float4(0.f, 0.f, 0.f, 0.f);
        if (a_ok) av = *(const float4*)(Arow + k0 + a_c);
        float4 bv;
        if (MODE == 1) bv = *(const float4*)(Brow_nt + k0 + a_c);
        else           bv = *(const float4*)(B + (size_t)(k0 + b_r) * N + bn + b_c);

        As[a_c + 0][a_r] = av.x; As[a_c + 1][a_r] = av.y;
        As[a_c + 2][a_r] = av.z; As[a_c + 3][a_r] = av.w;
        if (MODE == 1) {
            Bs[a_c + 0][a_r] = bv.x; Bs[a_c + 1][a_r] = bv.y;
            Bs[a_c + 2][a_r] = bv.z; Bs[a_c + 3][a_r] = bv.w;
        } else {
            *(float4*)&Bs[b_r][b_c] = bv;
        }
        __syncthreads();
#pragma unroll
        for (int kk = 0; kk < 16; kk++) {
            float4 a4 = *(const float4*)&As[kk][ty << 2];
            float4 b4 = *(const float4*)&Bs[kk][tx << 2];
            float aa[4] = {a4.x, a4.y, a4.z, a4.w};
            float bb[4] = {b4.x, b4.y, b4.z, b4.w};
#pragma unroll
            for (int i = 0; i < 4; i++)
#pragma unroll
                for (int j = 0; j < 4; j++)
                    acc[i][j] = fmaf(aa[i], bb[j], acc[i][j]);
        }
        __syncthreads();
    }

#pragma unroll
    for (int i = 0; i < 4; i++) {
        int r = bm + (ty << 2) + i;
        if (MODE >= 2 && r >= cnt_e) continue;
        float4 v;
        float* vv = (float*)&v;
#pragma unroll
        for (int j = 0; j < 4; j++) {
            float u = acc[i][j];
            int c = bn + (tx << 2) + j;
            if (MODE != 1) u += bias[c];
            if (ACT == 1) u = fmaxf(u, 0.f) + log1pf(expf(-fabsf(u)));  // softplus
            else if (ACT == 2) u = u / (1.f + __expf(-u));              // silu
            vv[j] = u;
        }
        size_t crow;
        if (MODE == 0 || MODE == 1) crow = (size_t)r;
        else if (MODE == 2) crow = (size_t)(off_e + r);
        else {
            int tok = perm[off_e + r];
            float wv = wsc[tok];
            v.x *= wv; v.y *= wv; v.z *= wv; v.w *= wv;
            crow = (size_t)tok;
        }
        *(float4*)(C + crow * (size_t)N + bn + (tx << 2)) = v;
    }
}

// ---------------- skinny B/C projection (N=16 each) ----------------
__global__ void bc_k(const float* __restrict__ h,
                     const float* __restrict__ WB, const float* __restrict__ bB,
                     const float* __restrict__ WC, const float* __restrict__ bC,
                     float* __restrict__ Bm, float* __restrict__ Cm) {
    int t = blockIdx.x * 8 + (threadIdx.x >> 5);
    int c = threadIdx.x & 31;
    const float* W = (c < 16) ? WB : WC;
    int cc = c & 15;
    const float* hr = h + (size_t)t * D_DIM;
    float acc = 0.f;
#pragma unroll 4
    for (int k = 0; k < D_DIM; k++)
        acc = fmaf(hr[k], W[k * N_ST + cc], acc);
    if (c < 16) Bm[t * N_ST + cc] = acc + bB[cc];
    else        Cm[t * N_ST + cc] = acc + bC[cc];
}

// ---------------- SSM sequential scan ----------------
// grid (D/32, B), 512 threads: 32 d-groups x 16 n-lanes
__global__ void __launch_bounds__(512) scan_k(
    const float* __restrict__ h, const float* __restrict__ delta,
    const float* __restrict__ Bm, const float* __restrict__ Cm,
    const float* __restrict__ A_log, const float* __restrict__ Dp,
    float* __restrict__ y)
{
    const int b  = blockIdx.y;
    const int d0 = blockIdx.x * 32;
    const int tid = threadIdx.x;
    const int dg = tid >> 4;      // 0..31
    const int n  = tid & 15;
    const int d  = d0 + dg;

    const float a  = -expf(A_log[d * N_ST + n]);
    const float Dv = Dp[d];
    float hs = 0.f;

    __shared__ float xs[2][16][32], ds[2][16][32];
    __shared__ float bs[2][16][16], cs[2][16][16];

    const int lt = tid >> 5;      // 0..15 row for x/delta loads
    const int ld = tid & 31;      // col
    const int tt = (tid >> 4) & 15;  // row for B/C loads
    const int nn = tid & 15;

    const size_t tok0 = (size_t)b * SEQL;

    // preload chunk 0
    xs[0][lt][ld] = h[(tok0 + lt) * D_DIM + d0 + ld];
    ds[0][lt][ld] = delta[(tok0 + lt) * D_DIM + d0 + ld];
    if (tid < 256) bs[0][tt][nn] = Bm[(tok0 + tt) * N_ST + nn];
    else           cs[0][tt][nn] = Cm[(tok0 + tt) * N_ST + nn];
    __syncthreads();

    const int NCH = SEQL / 16;
    for (int c = 0; c < NCH; c++) {
        int buf = c & 1;
        // prefetch next chunk into registers
        float px = 0.f, pd = 0.f, pbc = 0.f;
        bool has = (c + 1) < NCH;
        if (has) {
            int t1 = (c + 1) * 16;
            px = h[(tok0 + t1 + lt) * D_DIM + d0 + ld];
            pd = delta[(tok0 + t1 + lt) * D_DIM + d0 + ld];
            pbc = (tid < 256) ? Bm[(tok0 + t1 + tt) * N_ST + nn]
                              : Cm[(tok0 + t1 + tt) * N_ST + nn];
        }
        int tbase = c * 16;
#pragma unroll
        for (int s = 0; s < 16; s++) {
            float xv = xs[buf][s][dg];
            float dv = ds[buf][s][dg];
            float Bv = bs[buf][s][n];
            float Cv = cs[buf][s][n];
            float barA = __expf(fminf(dv * a, 2.f));
            float barB = fminf(fmaxf(dv * Bv, -2.f), 2.f);
            hs = fminf(fmaxf(fmaf(barA, hs, barB * xv), -100.f), 100.f);
            float p = hs * Cv;
            p += __shfl_xor_sync(0xffffffffu, p, 1, 16);
            p += __shfl_xor_sync(0xffffffffu, p, 2, 16);
            p += __shfl_xor_sync(0xffffffffu, p, 4, 16);
            p += __shfl_xor_sync(0xffffffffu, p, 8, 16);
            if (n == 0)
                y[(tok0 + tbase + s) * D_DIM + d] = p + xv * Dv;
        }
        if (has) {
            int nb = buf ^ 1;
            xs[nb][lt][ld] = px;
            ds[nb][lt][ld] = pd;
            if (tid < 256) bs[nb][tt][nn] = pbc;
            else           cs[nb][tt][nn] = pbc;
        }
        __syncthreads();
    }
}

// ---------------- router (top-1) + bucket ----------------
__global__ void zero_cnt_k(int* cnt) { if (threadIdx.x < E_EXP) cnt[threadIdx.x] = 0; }

__global__ void router_k(const float* __restrict__ y,
                         const float* __restrict__ Wr, const float* __restrict__ br,
                         float* __restrict__ w, int* __restrict__ eid,
                         int* __restrict__ pos, int* __restrict__ cnt) {
    int t = blockIdx.x * 4 + (threadIdx.x >> 5);
    int lane = threadIdx.x & 31;
    float a0 = 0.f, a1 = 0.f, a2 = 0.f, a3 = 0.f;
    const float* yr = y + (size_t)t * D_DIM;
    for (int k = lane; k < D_DIM; k += 32) {
        float v = yr[k];
        float4 wr = *(const float4*)&Wr[k * 4];
        a0 = fmaf(v, wr.x, a0); a1 = fmaf(v, wr.y, a1);
        a2 = fmaf(v, wr.z, a2); a3 = fmaf(v, wr.w, a3);
    }
#pragma unroll
    for (int o = 16; o; o >>= 1) {
        a0 += __shfl_xor_sync(0xffffffffu, a0, o);
        a1 += __shfl_xor_sync(0xffffffffu, a1, o);
        a2 += __shfl_xor_sync(0xffffffffu, a2, o);
        a3 += __shfl_xor_sync(0xffffffffu, a3, o);
    }
    if (lane == 0) {
        float z[4] = {a0 + br[0], a1 + br[1], a2 + br[2], a3 + br[3]};
        int best = 0; float m = z[0];
#pragma unroll
        for (int e = 1; e < 4; e++) if (z[e] > m) { m = z[e]; best = e; }
        float s = 0.f;
#pragma unroll
        for (int e = 0; e < 4; e++) s += __expf(z[e] - m);
        w[t] = 1.f / s;
        eid[t] = best;
        pos[t] = atomicAdd(&cnt[best], 1);
    }
}

__global__ void offs_k(const int* __restrict__ cnt, int* __restrict__ offs) {
    if (threadIdx.x == 0) {
        int s = 0;
        for (int e = 0; e < E_EXP; e++) { offs[e] = s; s += cnt[e]; }
    }
}

__global__ void scatter_k(const int* __restrict__ eid, const int* __restrict__ pos,
                          const int* __restrict__ offs, int* __restrict__ perm) {
    int t = blockIdx.x * 256 + threadIdx.x;
    perm[offs[eid[t]] + pos[t]] = t;
}

// ---------------- add + layernorm ----------------
__device__ __forceinline__ float block_sum(float v, float* red) {
    int lane = threadIdx.x & 31, wid = threadIdx.x >> 5;
#pragma unroll
    for (int o = 16; o; o >>= 1) v += __shfl_xor_sync(0xffffffffu, v, o);
    if (lane == 0) red[wid] = v;
    __syncthreads();
    float r = (threadIdx.x < 8) ? red[threadIdx.x] : 0.f;
    if (wid == 0) {
#pragma unroll
        for (int o = 4; o; o >>= 1) r += __shfl_xor_sync(0xffffffffu, r, o);
        if (lane == 0) red[0] = r;
    }
    __syncthreads();
    float out = red[0];
    __syncthreads();
    return out;
}

__global__ void ln_k(const float* __restrict__ y, const float* __restrict__ m,
                     const float* __restrict__ g, const float* __restrict__ b,
                     float* __restrict__ h) {
    int t = blockIdx.x, tid = threadIdx.x;
    __shared__ float red[32];
    const float* yr = y + (size_t)t * D_DIM;
    const float* mr = m + (size_t)t * D_DIM;
    float o[3];
    float s = 0.f;
#pragma unroll
    for (int i = 0; i < 3; i++) {
        int idx = tid + i * 256;
        o[i] = yr[idx] + mr[idx];
        s += o[i];
    }
    s = block_sum(s, red);
    float mu = s * (1.f / D_DIM);
    float sq = 0.f;
#pragma unroll
    for (int i = 0; i < 3; i++) { float d = o[i] - mu; sq += d * d; }
    sq = block_sum(sq, red);
    float inv = rsqrtf(sq * (1.f / D_DIM) + 1e-5f);
#pragma unroll
    for (int i = 0; i < 3; i++) {
        int idx = tid + i * 256;
        h[(size_t)t * D_DIM + idx] = (o[i] - mu) * inv * g[idx] + b[idx];
    }
}

// ---------------- launcher ----------------
extern "C" void kernel_launch(void* const* d_in, const int* in_sizes, int n_in,
                              void* d_out, int out_size) {
    (void)in_sizes; (void)n_in; (void)out_size;
    const int*   x     = (const int*)  d_in[0];
    const float* embed = (const float*)d_in[1];
    const float* A_log = (const float*)d_in[2];
    const float* Dp    = (const float*)d_in[3];
    const float* Wd    = (const float*)d_in[4];
    const float* bd    = (const float*)d_in[5];
    const float* WB    = (const float*)d_in[6];
    const float* bB    = (const float*)d_in[7];
    const float* WC    = (const float*)d_in[8];
    const float* bC    = (const float*)d_in[9];
    const float* Wr    = (const float*)d_in[10];
    const float* br    = (const float*)d_in[11];
    const float* Wu    = (const float*)d_in[12];
    const float* bu    = (const float*)d_in[13];
    const float* Wo    = (const float*)d_in[14];
    const float* bo    = (const float*)d_in[15];
    const float* lng   = (const float*)d_in[16];
    const float* lnb   = (const float*)d_in[17];
    float* out = (float*)d_out;

    float *p_h, *p_delta, *p_Bm, *p_Cm, *p_y, *p_mout, *p_H, *p_w;
    int *p_eid, *p_pos, *p_perm, *p_cnt, *p_offs;
    cudaGetSymbolAddress((void**)&p_h, g_h);
    cudaGetSymbolAddress((void**)&p_delta, g_delta);
    cudaGetSymbolAddress((void**)&p_Bm, g_Bm);
    cudaGetSymbolAddress((void**)&p_Cm, g_Cm);
    cudaGetSymbolAddress((void**)&p_y, g_y);
    cudaGetSymbolAddress((void**)&p_mout, g_mout);
    cudaGetSymbolAddress((void**)&p_H, g_H);
    cudaGetSymbolAddress((void**)&p_w, g_w);
    cudaGetSymbolAddress((void**)&p_eid, g_eid);
    cudaGetSymbolAddress((void**)&p_pos, g_pos);
    cudaGetSymbolAddress((void**)&p_perm, g_perm);
    cudaGetSymbolAddress((void**)&p_cnt, g_cnt);
    cudaGetSymbolAddress((void**)&p_offs, g_offs);

    embed_gather_k<<<T_TOK, 192>>>(x, embed, p_h);

    for (int l = 0; l < NLYR; l++) {
        const float* Wd_l = Wd + (size_t)l * D_DIM * D_DIM;
        const float* bd_l = bd + (size_t)l * D_DIM;
        const float* WB_l = WB + (size_t)l * D_DIM * N_ST;
        const float* bB_l = bB + (size_t)l * N_ST;
        const float* WC_l = WC + (size_t)l * D_DIM * N_ST;
        const float* bC_l = bC + (size_t)l * N_ST;
        const float* Al_l = A_log + (size_t)l * D_DIM * N_ST;
        const float* Dp_l = Dp + (size_t)l * D_DIM;
        const float* Wr_l = Wr + (size_t)l * D_DIM * E_EXP;
        const float* br_l = br + (size_t)l * E_EXP;
        const float* Wu_l = Wu + (size_t)l * E_EXP * D_DIM * DFF_F;
        const float* bu_l = bu + (size_t)l * E_EXP * DFF_F;
        const float* Wo_l = Wo + (size_t)l * E_EXP * DFF_F * D_DIM;
        const float* bo_l = bo + (size_t)l * E_EXP * D_DIM;
        const float* g_l  = lng + (size_t)l * D_DIM;
        const float* b_l  = lnb + (size_t)l * D_DIM;

        // delta = softplus(h @ Wd + bd)
        gemm_k<0, 1><<<dim3(D_DIM / 64, T_TOK / 64), 256>>>(
            p_h, Wd_l, bd_l, p_delta, D_DIM, D_DIM, nullptr, nullptr, nullptr, nullptr);
        // Bm, Cm
        bc_k<<<T_TOK / 8, 256>>>(p_h, WB_l, bB_l, WC_l, bC_l, p_Bm, p_Cm);
        // sequential scan -> y
        scan_k<<<dim3(D_DIM / 32, BSZ), 512>>>(p_h, p_delta, p_Bm, p_Cm, Al_l, Dp_l, p_y);
        // router + bucketing
        zero_cnt_k<<<1, 32>>>(p_cnt);
        router_k<<<T_TOK / 4, 128>>>(p_y, Wr_l, br_l, p_w, p_eid, p_pos, p_cnt);
        offs_k<<<1, 32>>>(p_cnt, p_offs);
        scatter_k<<<T_TOK / 256, 256>>>(p_eid, p_pos, p_offs, p_perm);
        // MoE up: H = silu(gather(y) @ Wu[e] + bu[e])
        gemm_k<2, 2><<<dim3(DFF_F / 64, T_TOK / 64, E_EXP), 256>>>(
            p_y, Wu_l, bu_l, p_H, DFF_F, D_DIM, p_perm, nullptr, p_cnt, p_offs);
        // MoE down: mout[tok] = (H @ Wo[e] + bo[e]) * w[tok]
        gemm_k<3, 0><<<dim3(D_DIM / 64, T_TOK / 64, E_EXP), 256>>>(
            p_H, Wo_l, bo_l, p_mout, D_DIM, DFF_F, p_perm, p_w, p_cnt, p_offs);
        // h = LN(y + mout)
        ln_k<<<T_TOK, 256>>>(p_y, p_mout, g_l, b_l, p_h);
    }

    // logits = h @ embed.T  (NT GEMM)
    gemm_k<1, 0><<<dim3(V_VOC / 64, T_TOK / 64), 256>>>(
        p_h, embed, nullptr, out, V_VOC, D_DIM, nullptr, nullptr, nullptr, nullptr);
}

// round 2
// speedup vs baseline: 2.3284x; 2.3284x over previous
#include <cuda_runtime.h>
#include <cuda_bf16.h>
#include <math.h>
#include <stdint.h>

#define T_TOK 4096
#define D_DIM 768
#define N_ST  16
#define E_EXP 4
#define DFF_F 3072
#define V_VOC 32000
#define NLYR  4
#define BSZ   2
#define SEQL  2048

// ---------------- scratch (no allocations allowed) ----------------
__device__ float g_h[T_TOK * D_DIM];
__device__ float g_delta[T_TOK * D_DIM];
__device__ float g_Bm[T_TOK * N_ST];
__device__ float g_Cm[T_TOK * N_ST];
__device__ float g_y[T_TOK * D_DIM];
__device__ float g_mout[T_TOK * D_DIM];
__device__ float g_H[T_TOK * DFF_F];
__device__ float g_w[T_TOK];
__device__ int   g_eid[T_TOK];
__device__ int   g_pos[T_TOK];
__device__ int   g_perm[T_TOK];
__device__ int   g_cnt[E_EXP];
__device__ int   g_offs[E_EXP];

// ---------------- embed gather ----------------
__global__ void embed_gather_k(const int* __restrict__ x,
                               const float* __restrict__ embed,
                               float* __restrict__ h) {
    int t = blockIdx.x;
    int tok = x[t];
    const float4* src = (const float4*)(embed + (size_t)tok * D_DIM);
    float4* dst = (float4*)(h + (size_t)t * D_DIM);
    dst[threadIdx.x] = src[threadIdx.x];   // 192 threads * 4 = 768
}

// ---------------- tensor-core GEMM (split-bf16 = fp32 accuracy) ----------------
// MODE 0: dense NN (A[M,K], B[K,N] row-major) + bias + ACT
// MODE 1: dense NT (B[N,K] row-major), no bias/act (logits)
// MODE 2: MoE up: gather A rows via perm, bias+silu, compact C rows
// MODE 3: MoE down: compact A rows, scatter C rows via perm, (acc+bias)*w[tok]
// ACT: 0 none, 1 softplus, 2 silu
// Tile: M=128, N=64, K-step=32. 256 threads = 8 warps (4m x 2n), 32x32 per warp.

#define LDSM4(R0,R1,R2,R3,ADDR) \
    asm volatile("ldmatrix.sync.aligned.m8n8.x4.shared.b16 {%0,%1,%2,%3}, [%4];" \
        : "=r"(R0),"=r"(R1),"=r"(R2),"=r"(R3) : "r"(ADDR))
#define LDSM4T(R0,R1,R2,R3,ADDR) \
    asm volatile("ldmatrix.sync.aligned.m8n8.x4.trans.shared.b16 {%0,%1,%2,%3}, [%4];" \
        : "=r"(R0),"=r"(R1),"=r"(R2),"=r"(R3) : "r"(ADDR))
#define MMA_BF16(D,AV,BV) \
    asm volatile("mma.sync.aligned.m16n8k16.row.col.f32.bf16.bf16.f32 " \
        "{%0,%1,%2,%3}, {%4,%5,%6,%7}, {%8,%9}, {%0,%1,%2,%3};" \
        : "+f"((D)[0]),"+f"((D)[1]),"+f"((D)[2]),"+f"((D)[3]) \
        : "r"((AV)[0]),"r"((AV)[1]),"r"((AV)[2]),"r"((AV)[3]), \
          "r"((BV)[0]),"r"((BV)[1]))

__device__ __forceinline__ void splt(float v, uint32_t& h, uint32_t& l) {
    __nv_bfloat16 bh = __float2bfloat16(v);
    float r = v - __bfloat162float(bh);
    __nv_bfloat16 bl = __float2bfloat16(r);
    h = (uint32_t)__bfloat16_as_ushort(bh);
    l = (uint32_t)__bfloat16_as_ushort(bl);
}
__device__ __forceinline__ void split_pack(float a, float b, uint32_t& hp, uint32_t& lp) {
    uint32_t h0, l0, h1, l1;
    splt(a, h0, l0); splt(b, h1, l1);
    hp = h0 | (h1 << 16);
    lp = l0 | (l1 << 16);
}

#define PA 40   // A smem pitch in bf16 (80B: ldmatrix conflict-free)
#define PB 72   // B smem pitch (k-major) in bf16 (144B: conflict-free)

template<int MODE, int ACT>
__global__ void __launch_bounds__(256) gemm_tc(
    const float* __restrict__ A, const float* __restrict__ B,
    const float* __restrict__ bias, float* __restrict__ C,
    int N, int K,
    const int* __restrict__ perm, const float* __restrict__ wsc,
    const int* __restrict__ cnt, const int* __restrict__ offs)
{
    __shared__ __align__(16) __nv_bfloat16 Ah[128 * PA], Al[128 * PA];
    __shared__ __align__(16) __nv_bfloat16 Bh[2560], Bl[2560];   // max(64*40, 32*72)

    const int tid = threadIdx.x;
    const int bn = blockIdx.x * 64;
    const int bm = blockIdx.y * 128;

    int cnt_e = 0, off_e = 0;
    if (MODE >= 2) {
        int e = blockIdx.z;
        cnt_e = cnt[e];
        off_e = offs[e];
        if (bm >= cnt_e) return;
        B += (size_t)e * K * N;
        bias += (size_t)e * N;
    }

    // ----- global load index setup -----
    const int ar = tid >> 3;           // 0..31
    const int ac = (tid & 7) * 4;      // 0..28
    const float* arow[4];
#pragma unroll
    for (int i = 0; i < 4; i++) {
        int g = bm + ar + 32 * i;
        if (MODE == 0 || MODE == 1) arow[i] = A + (size_t)g * K;
        else if (MODE == 2) arow[i] = (g < cnt_e) ? A + (size_t)perm[off_e + g] * K : nullptr;
        else                arow[i] = (g < cnt_e) ? A + (size_t)(off_e + g) * K : nullptr;
    }
    const int bkr = tid >> 4;          // NN: 0..15
    const int bbc = (tid & 15) * 4;    // NN: 0..60
    const int bnr = tid >> 2;          // NT: 0..63
    const int bks = (tid & 3) * 8;     // NT: 0..24

    // ----- mma fragment address setup -----
    const int w = tid >> 5, lane = tid & 31;
    const int wm = (w >> 1) * 32, wn = (w & 1) * 32;
    const uint32_t sAh = (uint32_t)__cvta_generic_to_shared(Ah);
    const uint32_t sAl = (uint32_t)__cvta_generic_to_shared(Al);
    const uint32_t sBh = (uint32_t)__cvta_generic_to_shared(Bh);
    const uint32_t sBl = (uint32_t)__cvta_generic_to_shared(Bl);

    const uint32_t a_off = (uint32_t)((lane & 15) * (PA * 2) + ((lane >> 4) & 1) * 16);
    uint32_t aBase[2];
#pragma unroll
    for (int mi = 0; mi < 2; mi++)
        aBase[mi] = (uint32_t)((wm + mi * 16) * (PA * 2)) + a_off;

    uint32_t bBase[2];
    if (MODE == 1) {
        uint32_t b_off = (uint32_t)(((lane & 7) + ((lane >> 4) & 1) * 8) * (PA * 2)
                                    + ((lane >> 3) & 1) * 16);
#pragma unroll
        for (int ni2 = 0; ni2 < 2; ni2++)
            bBase[ni2] = (uint32_t)((wn + ni2 * 16) * (PA * 2)) + b_off;
    } else {
        uint32_t b_off = (uint32_t)((lane & 15) * (PB * 2) + ((lane >> 4) & 1) * 16);
#pragma unroll
        for (int ni2 = 0; ni2 < 2; ni2++)
            bBase[ni2] = (uint32_t)((wn + ni2 * 16) * 2) + b_off;
    }

    float acc[2][4][4];
#pragma unroll
    for (int mi = 0; mi < 2; mi++)
#pragma unroll
        for (int nj = 0; nj < 4; nj++)
#pragma unroll
            for (int q = 0; q < 4; q++) acc[mi][nj][q] = 0.f;

    float4 av[4], bv[2];

#define LOAD_G(K0) do {                                                          \
    _Pragma("unroll")                                                            \
    for (int i = 0; i < 4; i++)                                                  \
        av[i] = arow[i] ? *(const float4*)(arow[i] + (K0) + ac)                  \
                        : make_float4(0.f, 0.f, 0.f, 0.f);                       \
    if (MODE == 1) {                                                             \
        const float* p = B + (size_t)(bn + bnr) * K + (K0) + bks;                \
        bv[0] = *(const float4*)p;                                               \
        bv[1] = *(const float4*)(p + 4);                                         \
    } else {                                                                     \
        _Pragma("unroll")                                                        \
        for (int i = 0; i < 2; i++)                                              \
            bv[i] = *(const float4*)(B + (size_t)((K0) + bkr + 16 * i) * N + bn + bbc); \
    } } while (0)

#define STORE_S() do {                                                           \
    _Pragma("unroll")                                                            \
    for (int i = 0; i < 4; i++) {                                                \
        int row = ar + 32 * i;                                                   \
        uint32_t h0, l0, h1, l1;                                                 \
        split_pack(av[i].x, av[i].y, h0, l0);                                    \
        split_pack(av[i].z, av[i].w, h1, l1);                                    \
        uint32_t* pH = (uint32_t*)(Ah + row * PA + ac);                          \
        uint32_t* pL = (uint32_t*)(Al + row * PA + ac);                          \
        pH[0] = h0; pH[1] = h1; pL[0] = l0; pL[1] = l1;                          \
    }                                                                            \
    if (MODE == 1) {                                                             \
        float f[8] = {bv[0].x, bv[0].y, bv[0].z, bv[0].w,                        \
                      bv[1].x, bv[1].y, bv[1].z, bv[1].w};                       \
        uint32_t* pH = (uint32_t*)(Bh + bnr * PA + bks);                         \
        uint32_t* pL = (uint32_t*)(Bl + bnr * PA + bks);                         \
        _Pragma("unroll")                                                        \
        for (int j = 0; j < 4; j++) {                                            \
            uint32_t hp, lp;                                                     \
            split_pack(f[2 * j], f[2 * j + 1], hp, lp);                          \
            pH[j] = hp; pL[j] = lp;                                              \
        }                                                                        \
    } else {                                                                     \
        _Pragma("unroll")                                                        \
        for (int i = 0; i < 2; i++) {                                            \
            uint32_t h0, l0, h1, l1;                                             \
            split_pack(bv[i].x, bv[i].y, h0, l0);                                \
            split_pack(bv[i].z, bv[i].w, h1, l1);                                \
            uint32_t* pH = (uint32_t*)(Bh + (bkr + 16 * i) * PB + bbc);          \
            uint32_t* pL = (uint32_t*)(Bl + (bkr + 16 * i) * PB + bbc);          \
            pH[0] = h0; pH[1] = h1; pL[0] = l0; pL[1] = l1;                      \
        }                                                                        \
    } } while (0)

    LOAD_G(0);
    for (int k0 = 0; k0 < K; k0 += 32) {
        STORE_S();
        __syncthreads();
        if (k0 + 32 < K) LOAD_G(k0 + 32);

#pragma unroll
        for (int kk = 0; kk < 32; kk += 16) {
            uint32_t ah[2][4], alr[2][4], bhf[4][2], blf[4][2];
#pragma unroll
            for (int mi = 0; mi < 2; mi++) {
                uint32_t adH = sAh + aBase[mi] + kk * 2;
                uint32_t adL = sAl + aBase[mi] + kk * 2;
                LDSM4(ah[mi][0], ah[mi][1], ah[mi][2], ah[mi][3], adH);
                LDSM4(alr[mi][0], alr[mi][1], alr[mi][2], alr[mi][3], adL);
            }
#pragma unroll
            for (int ni2 = 0; ni2 < 2; ni2++) {
                uint32_t r0, r1, r2, r3;
                if (MODE == 1) {
                    uint32_t adH = sBh + bBase[ni2] + kk * 2;
                    uint32_t adL = sBl + bBase[ni2] + kk * 2;
                    LDSM4(r0, r1, r2, r3, adH);
                    bhf[2 * ni2][0] = r0; bhf[2 * ni2][1] = r1;
                    bhf[2 * ni2 + 1][0] = r2; bhf[2 * ni2 + 1][1] = r3;
                    LDSM4(r0, r1, r2, r3, adL);
                    blf[2 * ni2][0] = r0; blf[2 * ni2][1] = r1;
                    blf[2 * ni2 + 1][0] = r2; blf[2 * ni2 + 1][1] = r3;
                } else {
                    uint32_t adH = sBh + bBase[ni2] + kk * (PB * 2);
                    uint32_t adL = sBl + bBase[ni2] + kk * (PB * 2);
                    LDSM4T(r0, r1, r2, r3, adH);
                    bhf[2 * ni2][0] = r0; bhf[2 * ni2][1] = r1;
                    bhf[2 * ni2 + 1][0] = r2; bhf[2 * ni2 + 1][1] = r3;
                    LDSM4T(r0, r1, r2, r3, adL);
                    blf[2 * ni2][0] = r0; blf[2 * ni2][1] = r1;
                    blf[2 * ni2 + 1][0] = r2; blf[2 * ni2 + 1][1] = r3;
                }
            }
#pragma unroll
            for (int mi = 0; mi < 2; mi++)
#pragma unroll
                for (int nj = 0; nj < 4; nj++) {
                    MMA_BF16(acc[mi][nj], ah[mi], bhf[nj]);
                    MMA_BF16(acc[mi][nj], ah[mi], blf[nj]);
                    MMA_BF16(acc[mi][nj], alr[mi], bhf[nj]);
                }
        }
        __syncthreads();
    }

    // ----- epilogue -----
#pragma unroll
    for (int mi = 0; mi < 2; mi++) {
#pragma unroll
        for (int half = 0; half < 2; half++) {
            int tr = wm + mi * 16 + (lane >> 2) + half * 8;
            size_t orow;
            float scale = 1.f;
            bool valid = true;
            if (MODE == 0 || MODE == 1) {
                orow = (size_t)(bm + tr);
            } else {
                int g = bm + tr;
                valid = g < cnt_e;
                if (MODE == 2) orow = (size_t)(off_e + g);
                else {
                    int tok = valid ? perm[off_e + g] : 0;
                    scale = valid ? wsc[tok] : 0.f;
                    orow = (size_t)tok;
                }
            }
            if (!valid) continue;
#pragma unroll
            for (int nj = 0; nj < 4; nj++) {
                int col = bn + wn + nj * 8 + (lane & 3) * 2;
                float u0 = acc[mi][nj][half * 2 + 0];
                float u1 = acc[mi][nj][half * 2 + 1];
                if (MODE != 1) {
                    float2 bb = *(const float2*)&bias[col];
                    u0 += bb.x; u1 += bb.y;
                }
                if (ACT == 1) {
                    u0 = fmaxf(u0, 0.f) + log1pf(expf(-fabsf(u0)));
                    u1 = fmaxf(u1, 0.f) + log1pf(expf(-fabsf(u1)));
                } else if (ACT == 2) {
                    u0 = u0 / (1.f + __expf(-u0));
                    u1 = u1 / (1.f + __expf(-u1));
                }
                if (MODE == 3) { u0 *= scale; u1 *= scale; }
                *(float2*)(C + orow * (size_t)N + col) = make_float2(u0, u1);
            }
        }
    }
}

// ---------------- skinny B/C projection (N=16 each) ----------------
__global__ void bc_k(const float* __restrict__ h,
                     const float* __restrict__ WB, const float* __restrict__ bB,
                     const float* __restrict__ WC, const float* __restrict__ bC,
                     float* __restrict__ Bm, float* __restrict__ Cm) {
    int t = blockIdx.x * 8 + (threadIdx.x >> 5);
    int c = threadIdx.x & 31;
    const float* W = (c < 16) ? WB : WC;
    int cc = c & 15;
    const float* hr = h + (size_t)t * D_DIM;
    float acc = 0.f;
#pragma unroll 4
    for (int k = 0; k < D_DIM; k++)
        acc = fmaf(hr[k], W[k * N_ST + cc], acc);
    if (c < 16) Bm[t * N_ST + cc] = acc + bB[cc];
    else        Cm[t * N_ST + cc] = acc + bC[cc];
}

// ---------------- SSM sequential scan ----------------
__global__ void __launch_bounds__(512) scan_k(
    const float* __restrict__ h, const float* __restrict__ delta,
    const float* __restrict__ Bm, const float* __restrict__ Cm,
    const float* __restrict__ A_log, const float* __restrict__ Dp,
    float* __restrict__ y)
{
    const int b  = blockIdx.y;
    const int d0 = blockIdx.x * 32;
    const int tid = threadIdx.x;
    const int dg = tid >> 4;
    const int n  = tid & 15;
    const int d  = d0 + dg;

    const float a  = -expf(A_log[d * N_ST + n]);
    const float Dv = Dp[d];
    float hs = 0.f;

    __shared__ float xs[2][16][32], ds[2][16][32];
    __shared__ float bs[2][16][16], cs[2][16][16];

    const int lt = tid >> 5;
    const int ld = tid & 31;
    const int tt = (tid >> 4) & 15;
    const int nn = tid & 15;

    const size_t tok0 = (size_t)b * SEQL;

    xs[0][lt][ld] = h[(tok0 + lt) * D_DIM + d0 + ld];
    ds[0][lt][ld] = delta[(tok0 + lt) * D_DIM + d0 + ld];
    if (tid < 256) bs[0][tt][nn] = Bm[(tok0 + tt) * N_ST + nn];
    else           cs[0][tt][nn] = Cm[(tok0 + tt) * N_ST + nn];
    __syncthreads();

    const int NCH = SEQL / 16;
    for (int c = 0; c < NCH; c++) {
        int buf = c & 1;
        float px = 0.f, pd = 0.f, pbc = 0.f;
        bool has = (c + 1) < NCH;
        if (has) {
            int t1 = (c + 1) * 16;
            px = h[(tok0 + t1 + lt) * D_DIM + d0 + ld];
            pd = delta[(tok0 + t1 + lt) * D_DIM + d0 + ld];
            pbc = (tid < 256) ? Bm[(tok0 + t1 + tt) * N_ST + nn]
                              : Cm[(tok0 + t1 + tt) * N_ST + nn];
        }
        int tbase = c * 16;
#pragma unroll
        for (int s = 0; s < 16; s++) {
            float xv = xs[buf][s][dg];
            float dv = ds[buf][s][dg];
            float Bv = bs[buf][s][n];
            float Cv = cs[buf][s][n];
            float barA = __expf(fminf(dv * a, 2.f));
            float barB = fminf(fmaxf(dv * Bv, -2.f), 2.f);
            hs = fminf(fmaxf(fmaf(barA, hs, barB * xv), -100.f), 100.f);
            float p = hs * Cv;
            p += __shfl_xor_sync(0xffffffffu, p, 1, 16);
            p += __shfl_xor_sync(0xffffffffu, p, 2, 16);
            p += __shfl_xor_sync(0xffffffffu, p, 4, 16);
            p += __shfl_xor_sync(0xffffffffu, p, 8, 16);
            if (n == 0)
                y[(tok0 + tbase + s) * D_DIM + d] = p + xv * Dv;
        }
        if (has) {
            int nb = buf ^ 1;
            xs[nb][lt][ld] = px;
            ds[nb][lt][ld] = pd;
            if (tid < 256) bs[nb][tt][nn] = pbc;
            else           cs[nb][tt][nn] = pbc;
        }
        __syncthreads();
    }
}

// ---------------- router (top-1) + bucket ----------------
__global__ void zero_cnt_k(int* cnt) { if (threadIdx.x < E_EXP) cnt[threadIdx.x] = 0; }

__global__ void router_k(const float* __restrict__ y,
                         const float* __restrict__ Wr, const float* __restrict__ br,
                         float* __restrict__ w, int* __restrict__ eid,
                         int* __restrict__ pos, int* __restrict__ cnt) {
    int t = blockIdx.x * 4 + (threadIdx.x >> 5);
    int lane = threadIdx.x & 31;
    float a0 = 0.f, a1 = 0.f, a2 = 0.f, a3 = 0.f;
    const float* yr = y + (size_t)t * D_DIM;
    for (int k = lane; k < D_DIM; k += 32) {
        float v = yr[k];
        float4 wr = *(const float4*)&Wr[k * 4];
        a0 = fmaf(v, wr.x, a0); a1 = fmaf(v, wr.y, a1);
        a2 = fmaf(v, wr.z, a2); a3 = fmaf(v, wr.w, a3);
    }
#pragma unroll
    for (int o = 16; o; o >>= 1) {
        a0 += __shfl_xor_sync(0xffffffffu, a0, o);
        a1 += __shfl_xor_sync(0xffffffffu, a1, o);
        a2 += __shfl_xor_sync(0xffffffffu, a2, o);
        a3 += __shfl_xor_sync(0xffffffffu, a3, o);
    }
    if (lane == 0) {
        float z[4] = {a0 + br[0], a1 + br[1], a2 + br[2], a3 + br[3]};
        int best = 0; float m = z[0];
#pragma unroll
        for (int e = 1; e < 4; e++) if (z[e] > m) { m = z[e]; best = e; }
        float s = 0.f;
#pragma unroll
        for (int e = 0; e < 4; e++) s += __expf(z[e] - m);
        w[t] = 1.f / s;
        eid[t] = best;
        pos[t] = atomicAdd(&cnt[best], 1);
    }
}

__global__ void offs_k(const int* __restrict__ cnt, int* __restrict__ offs) {
    if (threadIdx.x == 0) {
        int s = 0;
        for (int e = 0; e < E_EXP; e++) { offs[e] = s; s += cnt[e]; }
    }
}

__global__ void scatter_k(const int* __restrict__ eid, const int* __restrict__ pos,
                          const int* __restrict__ offs, int* __restrict__ perm) {
    int t = blockIdx.x * 256 + threadIdx.x;
    perm[offs[eid[t]] + pos[t]] = t;
}

// ---------------- add + layernorm ----------------
__device__ __forceinline__ float block_sum(float v, float* red) {
    int lane = threadIdx.x & 31, wid = threadIdx.x >> 5;
#pragma unroll
    for (int o = 16; o; o >>= 1) v += __shfl_xor_sync(0xffffffffu, v, o);
    if (lane == 0) red[wid] = v;
    __syncthreads();
    float r = (threadIdx.x < 8) ? red[threadIdx.x] : 0.f;
    if (wid == 0) {
#pragma unroll
        for (int o = 4; o; o >>= 1) r += __shfl_xor_sync(0xffffffffu, r, o);
        if (lane == 0) red[0] = r;
    }
    __syncthreads();
    float out = red[0];
    __syncthreads();
    return out;
}

__global__ void ln_k(const float* __restrict__ y, const float* __restrict__ m,
                     const float* __restrict__ g, const float* __restrict__ b,
                     float* __restrict__ h) {
    int t = blockIdx.x, tid = threadIdx.x;
    __shared__ float red[32];
    const float* yr = y + (size_t)t * D_DIM;
    const float* mr = m + (size_t)t * D_DIM;
    float o[3];
    float s = 0.f;
#pragma unroll
    for (int i = 0; i < 3; i++) {
        int idx = tid + i * 256;
        o[i] = yr[idx] + mr[idx];
        s += o[i];
    }
    s = block_sum(s, red);
    float mu = s * (1.f / D_DIM);
    float sq = 0.f;
#pragma unroll
    for (int i = 0; i < 3; i++) { float d = o[i] - mu; sq += d * d; }
    sq = block_sum(sq, red);
    float inv = rsqrtf(sq * (1.f / D_DIM) + 1e-5f);
#pragma unroll
    for (int i = 0; i < 3; i++) {
        int idx = tid + i * 256;
        h[(size_t)t * D_DIM + idx] = (o[i] - mu) * inv * g[idx] + b[idx];
    }
}

// ---------------- launcher ----------------
extern "C" void kernel_launch(void* const* d_in, const int* in_sizes, int n_in,
                              void* d_out, int out_size) {
    (void)in_sizes; (void)n_in; (void)out_size;
    const int*   x     = (const int*)  d_in[0];
    const float* embed = (const float*)d_in[1];
    const float* A_log = (const float*)d_in[2];
    const float* Dp    = (const float*)d_in[3];
    const float* Wd    = (const float*)d_in[4];
    const float* bd    = (const float*)d_in[5];
    const float* WB    = (const float*)d_in[6];
    const float* bB    = (const float*)d_in[7];
    const float* WC    = (const float*)d_in[8];
    const float* bC    = (const float*)d_in[9];
    const float* Wr    = (const float*)d_in[10];
    const float* br    = (const float*)d_in[11];
    const float* Wu    = (const float*)d_in[12];
    const float* bu    = (const float*)d_in[13];
    const float* Wo    = (const float*)d_in[14];
    const float* bo    = (const float*)d_in[15];
    const float* lng   = (const float*)d_in[16];
    const float* lnb   = (const float*)d_in[17];
    float* out = (float*)d_out;

    float *p_h, *p_delta, *p_Bm, *p_Cm, *p_y, *p_mout, *p_H, *p_w;
    int *p_eid, *p_pos, *p_perm, *p_cnt, *p_offs;
    cudaGetSymbolAddress((void**)&p_h, g_h);
    cudaGetSymbolAddress((void**)&p_delta, g_delta);
    cudaGetSymbolAddress((void**)&p_Bm, g_Bm);
    cudaGetSymbolAddress((void**)&p_Cm, g_Cm);
    cudaGetSymbolAddress((void**)&p_y, g_y);
    cudaGetSymbolAddress((void**)&p_mout, g_mout);
    cudaGetSymbolAddress((void**)&p_H, g_H);
    cudaGetSymbolAddress((void**)&p_w, g_w);
    cudaGetSymbolAddress((void**)&p_eid, g_eid);
    cudaGetSymbolAddress((void**)&p_pos, g_pos);
    cudaGetSymbolAddress((void**)&p_perm, g_perm);
    cudaGetSymbolAddress((void**)&p_cnt, g_cnt);
    cudaGetSymbolAddress((void**)&p_offs, g_offs);

    embed_gather_k<<<T_TOK, 192>>>(x, embed, p_h);

    for (int l = 0; l < NLYR; l++) {
        const float* Wd_l = Wd + (size_t)l * D_DIM * D_DIM;
        const float* bd_l = bd + (size_t)l * D_DIM;
        const float* WB_l = WB + (size_t)l * D_DIM * N_ST;
        const float* bB_l = bB + (size_t)l * N_ST;
        const float* WC_l = WC + (size_t)l * D_DIM * N_ST;
        const float* bC_l = bC + (size_t)l * N_ST;
        const float* Al_l = A_log + (size_t)l * D_DIM * N_ST;
        const float* Dp_l = Dp + (size_t)l * D_DIM;
        const float* Wr_l = Wr + (size_t)l * D_DIM * E_EXP;
        const float* br_l = br + (size_t)l * E_EXP;
        const float* Wu_l = Wu + (size_t)l * E_EXP * D_DIM * DFF_F;
        const float* bu_l = bu + (size_t)l * E_EXP * DFF_F;
        const float* Wo_l = Wo + (size_t)l * E_EXP * DFF_F * D_DIM;
        const float* bo_l = bo + (size_t)l * E_EXP * D_DIM;
        const float* g_l  = lng + (size_t)l * D_DIM;
        const float* b_l  = lnb + (size_t)l * D_DIM;

        // delta = softplus(h @ Wd + bd)
        gemm_tc<0, 1><<<dim3(D_DIM / 64, T_TOK / 128), 256>>>(
            p_h, Wd_l, bd_l, p_delta, D_DIM, D_DIM, nullptr, nullptr, nullptr, nullptr);
        // Bm, Cm
        bc_k<<<T_TOK / 8, 256>>>(p_h, WB_l, bB_l, WC_l, bC_l, p_Bm, p_Cm);
        // sequential scan -> y
        scan_k<<<dim3(D_DIM / 32, BSZ), 512>>>(p_h, p_delta, p_Bm, p_Cm, Al_l, Dp_l, p_y);
        // router + bucketing
        zero_cnt_k<<<1, 32>>>(p_cnt);
        router_k<<<T_TOK / 4, 128>>>(p_y, Wr_l, br_l, p_w, p_eid, p_pos, p_cnt);
        offs_k<<<1, 32>>>(p_cnt, p_offs);
        scatter_k<<<T_TOK / 256, 256>>>(p_eid, p_pos, p_offs, p_perm);
        // MoE up: H = silu(gather(y) @ Wu[e] + bu[e])
        gemm_tc<2, 2><<<dim3(DFF_F / 64, T_TOK / 128, E_EXP), 256>>>(
            p_y, Wu_l, bu_l, p_H, DFF_F, D_DIM, p_perm, nullptr, p_cnt, p_offs);
        // MoE down: mout[tok] = (H @ Wo[e] + bo[e]) * w[tok]
        gemm_tc<3, 0><<<dim3(D_DIM / 64, T_TOK / 128, E_EXP), 256>>>(
            p_H, Wo_l, bo_l, p_mout, D_DIM, DFF_F, p_perm, p_w, p_cnt, p_offs);
        // h = LN(y + mout)
        ln_k<<<T_TOK, 256>>>(p_y, p_mout, g_l, b_l, p_h);
    }

    // logits = h @ embed.T  (NT GEMM)
    gemm_tc<1, 0><<<dim3(V_VOC / 64, T_TOK / 128), 256>>>(
        p_h, embed, nullptr, out, V_VOC, D_DIM, nullptr, nullptr, nullptr, nullptr);
}